// round 2
// baseline (speedup 1.0000x reference)
#include <cuda_runtime.h>
#include <math.h>

#define NB   64
#define TT   1380
#define XDIM 96
#define HDIM 192
#define CNUM 345

// Scratch (allocation-free: __device__ globals)
__device__ __align__(128) float g_T1[(size_t)NB * CNUM * XDIM];   // W2 @ X   : [B,345,96]
__device__ __align__(128) float g_Y [(size_t)NB * CNUM * HDIM];   // T1 @ W1  : [B,345,192]
__device__ __align__(128) float g_S [(size_t)NB * CNUM * TT];     // logits/P : [B,345,1380]

#define BM 128
#define BN 128
#define BK 8
#define TM 8
#define TN 8
#define NTHREADS 256

// C[M,N] = alpha * A[M,K] @ op(B),  op(B)=B[K,N] (NN) or B[N,K]^T (NT).
// Batched via blockIdx.z with strides (stride 0 = broadcast).
template<bool TRANSB>
__global__ __launch_bounds__(NTHREADS)
void gemm_kernel(const float* __restrict__ A, const float* __restrict__ Bm,
                 float* __restrict__ C, int M, int N, int K,
                 long long sA, long long sB, long long sC, float alpha)
{
    __shared__ float As[BK][BM];
    __shared__ float Bs[BK][BN];

    const int b = blockIdx.z;
    A  += (long long)b * sA;
    Bm += (long long)b * sB;
    C  += (long long)b * sC;

    const int rowBase = blockIdx.y * BM;
    const int colBase = blockIdx.x * BN;
    const int tid = threadIdx.x;
    const int ty = tid >> 4;   // 0..15
    const int tx = tid & 15;   // 0..15

    float acc[TM][TN];
    #pragma unroll
    for (int i = 0; i < TM; i++)
        #pragma unroll
        for (int j = 0; j < TN; j++) acc[i][j] = 0.0f;

    for (int k0 = 0; k0 < K; k0 += BK) {
        // ---- load A tile [BM x BK], K-contiguous rows ----
        {
            int rowA = tid >> 1;
            int colA = (tid & 1) * 4;
            int gR = rowBase + rowA;
            int gC = k0 + colA;
            float4 v = make_float4(0.f, 0.f, 0.f, 0.f);
            if (gR < M) {
                const float* p = A + (size_t)gR * K + gC;
                if (gC + 3 < K) v = *(const float4*)p;
                else {
                    if (gC     < K) v.x = p[0];
                    if (gC + 1 < K) v.y = p[1];
                    if (gC + 2 < K) v.z = p[2];
                }
            }
            As[colA    ][rowA] = v.x;
            As[colA + 1][rowA] = v.y;
            As[colA + 2][rowA] = v.z;
            As[colA + 3][rowA] = v.w;
        }
        // ---- load B tile ----
        if (TRANSB) {
            // B is [N,K] row-major (K contiguous)
            int rowB = tid >> 1;
            int colB = (tid & 1) * 4;
            int gN = colBase + rowB;
            int gK = k0 + colB;
            float4 v = make_float4(0.f, 0.f, 0.f, 0.f);
            if (gN < N) {
                const float* p = Bm + (size_t)gN * K + gK;
                if (gK + 3 < K) v = *(const float4*)p;
                else {
                    if (gK     < K) v.x = p[0];
                    if (gK + 1 < K) v.y = p[1];
                    if (gK + 2 < K) v.z = p[2];
                }
            }
            Bs[colB    ][rowB] = v.x;
            Bs[colB + 1][rowB] = v.y;
            Bs[colB + 2][rowB] = v.z;
            Bs[colB + 3][rowB] = v.w;
        } else {
            // B is [K,N] row-major (N contiguous)
            int kb = tid >> 5;          // 0..7
            int cb = (tid & 31) * 4;    // 0..124
            int gK = k0 + kb;
            int gC = colBase + cb;
            float4 v = make_float4(0.f, 0.f, 0.f, 0.f);
            if (gK < K) {
                const float* p = Bm + (size_t)gK * N + gC;
                if (gC + 3 < N) v = *(const float4*)p;
                else {
                    if (gC     < N) v.x = p[0];
                    if (gC + 1 < N) v.y = p[1];
                    if (gC + 2 < N) v.z = p[2];
                }
            }
            *(float4*)&Bs[kb][cb] = v;
        }
        __syncthreads();

        #pragma unroll
        for (int kk = 0; kk < BK; kk++) {
            float a[TM], bb[TN];
            *(float4*)&a[0]  = *(const float4*)&As[kk][ty * TM];
            *(float4*)&a[4]  = *(const float4*)&As[kk][ty * TM + 4];
            *(float4*)&bb[0] = *(const float4*)&Bs[kk][tx * TN];
            *(float4*)&bb[4] = *(const float4*)&Bs[kk][tx * TN + 4];
            #pragma unroll
            for (int i = 0; i < TM; i++)
                #pragma unroll
                for (int j = 0; j < TN; j++)
                    acc[i][j] = fmaf(a[i], bb[j], acc[i][j]);
        }
        __syncthreads();
    }

    // ---- epilogue ----
    #pragma unroll
    for (int i = 0; i < TM; i++) {
        int r = rowBase + ty * TM + i;
        if (r < M) {
            float* cp = C + (size_t)r * N;
            #pragma unroll
            for (int j = 0; j < TN; j += 4) {
                int c = colBase + tx * TN + j;
                if (c + 3 < N) {
                    float4 v = make_float4(acc[i][j] * alpha, acc[i][j+1] * alpha,
                                           acc[i][j+2] * alpha, acc[i][j+3] * alpha);
                    *(float4*)&cp[c] = v;
                } else {
                    #pragma unroll
                    for (int q = 0; q < 4; q++)
                        if (c + q < N) cp[c + q] = acc[i][j + q] * alpha;
                }
            }
        }
    }
}

// Row softmax over length TT=1380, one block (256 threads) per row.
// Register-resident: 1 read + 1 write of the row.
#define SM_ITER 6   // ceil(1380/256)
__global__ __launch_bounds__(256)
void softmax_kernel(float* __restrict__ S)
{
    const int row = blockIdx.x;
    float* p = S + (size_t)row * TT;
    const int tid = threadIdx.x;

    float v[SM_ITER];
    float m = -1e30f;
    #pragma unroll
    for (int i = 0; i < SM_ITER; i++) {
        int idx = tid + i * 256;
        v[i] = (idx < TT) ? p[idx] : -1e30f;
        m = fmaxf(m, v[i]);
    }

    __shared__ float red[8];
    #pragma unroll
    for (int o = 16; o > 0; o >>= 1) m = fmaxf(m, __shfl_xor_sync(0xffffffffu, m, o));
    if ((tid & 31) == 0) red[tid >> 5] = m;
    __syncthreads();
    float bm = red[0];
    #pragma unroll
    for (int w = 1; w < 8; w++) bm = fmaxf(bm, red[w]);
    __syncthreads();

    float s = 0.f;
    #pragma unroll
    for (int i = 0; i < SM_ITER; i++) {
        v[i] = __expf(v[i] - bm);   // -1e30 pad -> exp(..) == 0
        s += v[i];
    }
    #pragma unroll
    for (int o = 16; o > 0; o >>= 1) s += __shfl_xor_sync(0xffffffffu, s, o);
    if ((tid & 31) == 0) red[tid >> 5] = s;
    __syncthreads();
    float tot = 0.f;
    #pragma unroll
    for (int w = 0; w < 8; w++) tot += red[w];
    float inv = 1.0f / tot;

    #pragma unroll
    for (int i = 0; i < SM_ITER; i++) {
        int idx = tid + i * 256;
        if (idx < TT) p[idx] = v[i] * inv;
    }
}

extern "C" void kernel_launch(void* const* d_in, const int* in_sizes, int n_in,
                              void* d_out, int out_size)
{
    // Identify inputs by element count (all distinct) — robust to ordering.
    const float *X = nullptr, *H = nullptr, *W1 = nullptr, *W2 = nullptr;
    for (int i = 0; i < n_in; i++) {
        int s = in_sizes[i];
        if      (s == NB * TT * XDIM) X  = (const float*)d_in[i];
        else if (s == NB * TT * HDIM) H  = (const float*)d_in[i];
        else if (s == XDIM * HDIM)    W1 = (const float*)d_in[i];
        else if (s == CNUM * TT)      W2 = (const float*)d_in[i];
    }
    float* out = (float*)d_out;

    float *T1, *Y, *S;
    cudaGetSymbolAddress((void**)&T1, g_T1);
    cudaGetSymbolAddress((void**)&Y,  g_Y);
    cudaGetSymbolAddress((void**)&S,  g_S);

    const float scale = (float)(1.0 / sqrt((double)XDIM * (double)HDIM));

    // K1: T1[b] = W2 @ X[b]           M=345 N=96  K=1380   (NN, A broadcast)
    gemm_kernel<false><<<dim3(1, 3, NB), NTHREADS>>>(
        W2, X, T1, CNUM, XDIM, TT,
        0LL, (long long)TT * XDIM, (long long)CNUM * XDIM, 1.0f);

    // K2: Y[b] = T1[b] @ W1           M=345 N=192 K=96     (NN, B broadcast)
    gemm_kernel<false><<<dim3(2, 3, NB), NTHREADS>>>(
        T1, W1, Y, CNUM, HDIM, XDIM,
        (long long)CNUM * XDIM, 0LL, (long long)CNUM * HDIM, 1.0f);

    // K3: S[b] = scale * Y[b] @ H[b]^T   M=345 N=1380 K=192  (NT)
    gemm_kernel<true><<<dim3(11, 3, NB), NTHREADS>>>(
        Y, H, S, CNUM, TT, HDIM,
        (long long)CNUM * HDIM, (long long)TT * HDIM, (long long)CNUM * TT, scale);

    // K4: softmax rows of S (in place)
    softmax_kernel<<<NB * CNUM, 256>>>(S);

    // K5: out[b] = P[b] @ H[b]        M=345 N=192 K=1380   (NN)
    gemm_kernel<false><<<dim3(2, 3, NB), NTHREADS>>>(
        S, H, out, CNUM, HDIM, TT,
        (long long)CNUM * TT, (long long)TT * HDIM, (long long)CNUM * HDIM, 1.0f);
}

// round 3
// speedup vs baseline: 1.9591x; 1.9591x over previous
#include <cuda_runtime.h>
#include <cstdint>
#include <math.h>

#define NB   64
#define TT   1380
#define XDIM 96
#define HDIM 192
#define CNUM 345

// Scratch (allocation-free: __device__ globals)
__device__ __align__(128) float g_T1[(size_t)NB * CNUM * XDIM];   // W2 @ X   : [B,345,96]
__device__ __align__(128) float g_Y [(size_t)NB * CNUM * HDIM];   // T1 @ W1  : [B,345,192]
__device__ __align__(128) float g_S [(size_t)NB * CNUM * TT];     // logits/P : [B,345,1380]

// ---------------------------------------------------------------------------
// Tensor-core GEMM: C[M,N] = alpha * A[M,K] @ op(B), fp32 in/out.
// op(B) = B[K,N] (TRANSB=false) or B[N,K]^T (TRANSB=true).
// Uses 3xTF32 split-precision mma (m16n8k8) => ~fp32 accuracy.
// Block tile 128x128, BK=16, 8 warps (4x2), warp tile 32x64.
// ---------------------------------------------------------------------------
#define BM 128
#define BN 128
#define BK 16
#define AST 20            // As row stride (BK + 4), keeps float4 alignment
#define BST_NT 20         // Bs k-major row stride (BK + 4)
#define BST_NN 132        // Bs n-major row stride (BN + 4)

__device__ __forceinline__ void split_tf32(float f, uint32_t& big, uint32_t& small) {
    uint32_t b;
    asm("cvt.rna.tf32.f32 %0, %1;" : "=r"(b) : "f"(f));
    float s = f - __uint_as_float(b);
    uint32_t sm;
    asm("cvt.rna.tf32.f32 %0, %1;" : "=r"(sm) : "f"(s));
    big = b; small = sm;
}

__device__ __forceinline__ void mma8(float* c, const uint32_t* a, const uint32_t* b) {
    asm volatile(
        "mma.sync.aligned.m16n8k8.row.col.f32.tf32.tf32.f32 "
        "{%0,%1,%2,%3}, {%4,%5,%6,%7}, {%8,%9}, {%0,%1,%2,%3};"
        : "+f"(c[0]), "+f"(c[1]), "+f"(c[2]), "+f"(c[3])
        : "r"(a[0]), "r"(a[1]), "r"(a[2]), "r"(a[3]), "r"(b[0]), "r"(b[1]));
}

template<bool TRANSB>
__global__ __launch_bounds__(256, 1)
void gemm_tc(const float* __restrict__ A, const float* __restrict__ Bm,
             float* __restrict__ C, int M, int N, int K,
             long long sA, long long sB, long long sC, float alpha)
{
    constexpr int BS_SZ = TRANSB ? (BN * BST_NT) : (BK * BST_NN);
    __shared__ float As[BM * AST];
    __shared__ float Bs[BS_SZ];

    const int b = blockIdx.z;
    A  += (long long)b * sA;
    Bm += (long long)b * sB;
    C  += (long long)b * sC;

    const int rowBase = blockIdx.y * BM;
    const int colBase = blockIdx.x * BN;
    const int tid  = threadIdx.x;
    const int lane = tid & 31;
    const int warp = tid >> 5;
    const int warpM = warp >> 1;       // 0..3  -> 32-row slab
    const int warpN = warp & 1;        // 0..1  -> 64-col slab
    const int grp = lane >> 2;         // 0..7
    const int qid = lane & 3;          // 0..3

    // accumulators: 2 m-tiles x 8 n-tiles x 4 regs
    float acc[2][8][4];
    #pragma unroll
    for (int i = 0; i < 2; i++)
        #pragma unroll
        for (int j = 0; j < 8; j++)
            #pragma unroll
            for (int q = 0; q < 4; q++) acc[i][j][q] = 0.0f;

    for (int k0 = 0; k0 < K; k0 += BK) {
        // ---- load A tile [BM x BK], A is [M,K] k-contiguous. K % 4 == 0. ----
        #pragma unroll
        for (int i = 0; i < 2; i++) {
            int idx = tid + i * 256;          // 512 float4s
            int row = idx >> 2;
            int kq  = (idx & 3) * 4;
            int gR = rowBase + row;
            int gK = k0 + kq;
            float4 v = make_float4(0.f, 0.f, 0.f, 0.f);
            if (gR < M && gK < K)
                v = *(const float4*)(A + (size_t)gR * K + gK);
            *(float4*)&As[row * AST + kq] = v;
        }
        // ---- load B tile ----
        if (TRANSB) {
            // B is [N,K] row-major; store k-major Bs[n][k]
            #pragma unroll
            for (int i = 0; i < 2; i++) {
                int idx = tid + i * 256;
                int n  = idx >> 2;
                int kq = (idx & 3) * 4;
                int gN = colBase + n;
                int gK = k0 + kq;
                float4 v = make_float4(0.f, 0.f, 0.f, 0.f);
                if (gN < N && gK < K)
                    v = *(const float4*)(Bm + (size_t)gN * K + gK);
                *(float4*)&Bs[n * BST_NT + kq] = v;
            }
        } else {
            // B is [K,N] row-major; store n-major Bs[k][n]. N % 4 == 0.
            #pragma unroll
            for (int i = 0; i < 2; i++) {
                int idx = tid + i * 256;
                int k  = idx >> 5;            // 0..15
                int nq = (idx & 31) * 4;      // 0..124
                int gK = k0 + k;
                int gN = colBase + nq;
                float4 v = make_float4(0.f, 0.f, 0.f, 0.f);
                if (gK < K && gN < N)
                    v = *(const float4*)(Bm + (size_t)gK * N + gN);
                *(float4*)&Bs[k * BST_NN + nq] = v;
            }
        }
        __syncthreads();

        #pragma unroll
        for (int kk = 0; kk < BK; kk += 8) {
            // A fragments (2 m-tiles), split big/small
            uint32_t Ab[2][4], Al[2][4];
            #pragma unroll
            for (int mt = 0; mt < 2; mt++) {
                int r = warpM * 32 + mt * 16 + grp;
                float a0 = As[r * AST + kk + qid];
                float a1 = As[(r + 8) * AST + kk + qid];
                float a2 = As[r * AST + kk + qid + 4];
                float a3 = As[(r + 8) * AST + kk + qid + 4];
                split_tf32(a0, Ab[mt][0], Al[mt][0]);
                split_tf32(a1, Ab[mt][1], Al[mt][1]);
                split_tf32(a2, Ab[mt][2], Al[mt][2]);
                split_tf32(a3, Ab[mt][3], Al[mt][3]);
            }
            // B fragments (8 n-tiles), split big/small
            uint32_t Bb[8][2], Bl[8][2];
            #pragma unroll
            for (int nt = 0; nt < 8; nt++) {
                int n = warpN * 64 + nt * 8 + grp;
                float b0, b1;
                if (TRANSB) {
                    b0 = Bs[n * BST_NT + kk + qid];
                    b1 = Bs[n * BST_NT + kk + qid + 4];
                } else {
                    b0 = Bs[(kk + qid) * BST_NN + n];
                    b1 = Bs[(kk + qid + 4) * BST_NN + n];
                }
                split_tf32(b0, Bb[nt][0], Bl[nt][0]);
                split_tf32(b1, Bb[nt][1], Bl[nt][1]);
            }
            // 3xTF32 mma: D += Ab*Bb + Ab*Bl + Al*Bb
            #pragma unroll
            for (int mt = 0; mt < 2; mt++)
                #pragma unroll
                for (int nt = 0; nt < 8; nt++) {
                    mma8(acc[mt][nt], Ab[mt], Bb[nt]);
                    mma8(acc[mt][nt], Ab[mt], Bl[nt]);
                    mma8(acc[mt][nt], Al[mt], Bb[nt]);
                }
        }
        __syncthreads();
    }

    // ---- epilogue: c0,c1 at (r, c..c+1), c2,c3 at (r+8, c..c+1). N is even. ----
    #pragma unroll
    for (int mt = 0; mt < 2; mt++) {
        #pragma unroll
        for (int nt = 0; nt < 8; nt++) {
            int r = rowBase + warpM * 32 + mt * 16 + grp;
            int c = colBase + warpN * 64 + nt * 8 + qid * 2;
            if (c < N) {
                if (r < M) {
                    float2 v = make_float2(acc[mt][nt][0] * alpha, acc[mt][nt][1] * alpha);
                    *(float2*)(C + (size_t)r * N + c) = v;
                }
                if (r + 8 < M) {
                    float2 v = make_float2(acc[mt][nt][2] * alpha, acc[mt][nt][3] * alpha);
                    *(float2*)(C + (size_t)(r + 8) * N + c) = v;
                }
            }
        }
    }
}

// ---------------------------------------------------------------------------
// Row softmax over length TT=1380, one block (256 threads) per row.
// ---------------------------------------------------------------------------
#define SM_ITER 6   // ceil(1380/256)
__global__ __launch_bounds__(256)
void softmax_kernel(float* __restrict__ S)
{
    const int row = blockIdx.x;
    float* p = S + (size_t)row * TT;
    const int tid = threadIdx.x;

    float v[SM_ITER];
    float m = -1e30f;
    #pragma unroll
    for (int i = 0; i < SM_ITER; i++) {
        int idx = tid + i * 256;
        v[i] = (idx < TT) ? p[idx] : -1e30f;
        m = fmaxf(m, v[i]);
    }

    __shared__ float red[8];
    #pragma unroll
    for (int o = 16; o > 0; o >>= 1) m = fmaxf(m, __shfl_xor_sync(0xffffffffu, m, o));
    if ((tid & 31) == 0) red[tid >> 5] = m;
    __syncthreads();
    float bm = red[0];
    #pragma unroll
    for (int w = 1; w < 8; w++) bm = fmaxf(bm, red[w]);
    __syncthreads();

    float s = 0.f;
    #pragma unroll
    for (int i = 0; i < SM_ITER; i++) {
        v[i] = __expf(v[i] - bm);
        s += v[i];
    }
    #pragma unroll
    for (int o = 16; o > 0; o >>= 1) s += __shfl_xor_sync(0xffffffffu, s, o);
    if ((tid & 31) == 0) red[tid >> 5] = s;
    __syncthreads();
    float tot = 0.f;
    #pragma unroll
    for (int w = 0; w < 8; w++) tot += red[w];
    float inv = 1.0f / tot;

    #pragma unroll
    for (int i = 0; i < SM_ITER; i++) {
        int idx = tid + i * 256;
        if (idx < TT) p[idx] = v[i] * inv;
    }
}

extern "C" void kernel_launch(void* const* d_in, const int* in_sizes, int n_in,
                              void* d_out, int out_size)
{
    // Identify inputs by element count (all distinct) — robust to ordering.
    const float *X = nullptr, *H = nullptr, *W1 = nullptr, *W2 = nullptr;
    for (int i = 0; i < n_in; i++) {
        int s = in_sizes[i];
        if      (s == NB * TT * XDIM) X  = (const float*)d_in[i];
        else if (s == NB * TT * HDIM) H  = (const float*)d_in[i];
        else if (s == XDIM * HDIM)    W1 = (const float*)d_in[i];
        else if (s == CNUM * TT)      W2 = (const float*)d_in[i];
    }
    float* out = (float*)d_out;

    float *T1, *Y, *S;
    cudaGetSymbolAddress((void**)&T1, g_T1);
    cudaGetSymbolAddress((void**)&Y,  g_Y);
    cudaGetSymbolAddress((void**)&S,  g_S);

    const float scale = (float)(1.0 / sqrt((double)XDIM * (double)HDIM));

    // K1: T1[b] = W2 @ X[b]           M=345 N=96  K=1380   (NN, A broadcast)
    gemm_tc<false><<<dim3(1, 3, NB), 256>>>(
        W2, X, T1, CNUM, XDIM, TT,
        0LL, (long long)TT * XDIM, (long long)CNUM * XDIM, 1.0f);

    // K2: Y[b] = T1[b] @ W1           M=345 N=192 K=96     (NN, B broadcast)
    gemm_tc<false><<<dim3(2, 3, NB), 256>>>(
        T1, W1, Y, CNUM, HDIM, XDIM,
        (long long)CNUM * XDIM, 0LL, (long long)CNUM * HDIM, 1.0f);

    // K3: S[b] = scale * Y[b] @ H[b]^T   M=345 N=1380 K=192  (NT)
    gemm_tc<true><<<dim3(11, 3, NB), 256>>>(
        Y, H, S, CNUM, TT, HDIM,
        (long long)CNUM * HDIM, (long long)TT * HDIM, (long long)CNUM * TT, scale);

    // K4: softmax rows of S (in place)
    softmax_kernel<<<NB * CNUM, 256>>>(S);

    // K5: out[b] = P[b] @ H[b]        M=345 N=192 K=1380   (NN)
    gemm_tc<false><<<dim3(2, 3, NB), 256>>>(
        S, H, out, CNUM, HDIM, TT,
        (long long)CNUM * TT, (long long)TT * HDIM, (long long)CNUM * HDIM, 1.0f);
}

// round 10
// speedup vs baseline: 2.8631x; 1.4614x over previous
#include <cuda_runtime.h>
#include <cstdint>
#include <math.h>

#define NB   64
#define TT   1380
#define XDIM 96
#define HDIM 192
#define CNUM 345

// ---------------- scratch (allocation-free) ----------------
__device__ __align__(128) float g_T1 [(size_t)NB * CNUM * XDIM];   // [B,345,96]
__device__ __align__(128) float g_Y  [(size_t)NB * CNUM * HDIM];   // [B,345,192]
__device__ __align__(128) float g_S  [(size_t)NB * CNUM * TT];     // [B,345,1380]
__device__ __align__(128) float g_XT [(size_t)NB * XDIM * TT];     // [B,96,1380]
__device__ __align__(128) float g_HT [(size_t)NB * HDIM * TT];     // [B,192,1380]
__device__ __align__(128) float g_W1T[(size_t)HDIM * XDIM];        // [192,96]

__device__ __forceinline__ float tf32big(float f) {
    uint32_t r;
    asm("cvt.rna.tf32.f32 %0, %1;" : "=r"(r) : "f"(f));
    return __uint_as_float(r);
}

__device__ __forceinline__ void mma8(float* c, const uint32_t* a, const uint32_t* b) {
    asm volatile(
        "mma.sync.aligned.m16n8k8.row.col.f32.tf32.tf32.f32 "
        "{%0,%1,%2,%3}, {%4,%5,%6,%7}, {%8,%9}, {%0,%1,%2,%3};"
        : "+f"(c[0]), "+f"(c[1]), "+f"(c[2]), "+f"(c[3])
        : "r"(a[0]), "r"(a[1]), "r"(a[2]), "r"(a[3]), "r"(b[0]), "r"(b[1]));
}

// ---------------------------------------------------------------------------
// Split-precision (3xTF32) mma.sync GEMM:
//   C[M,N] = alpha * A[M,K] @ B[N,K]^T    (both operands K-major fp32)
// CTA tile 128x128, K-chunk 32 (4 phases of k8), 8 warps (warp tile 32x64).
// Smem holds tf32-split operands in MMA *fragment order* so each thread's
// A fragment is one ld.shared.128 and B fragment one ld.shared.64,
// with an XOR-by-kp plane swizzle for bank-conflict-free reads.
// Double-buffered smem + register prefetch to overlap LDG/STS with HMMA.
//
// Fragment layouts (per 32-float "stage" region offsets, in floats):
//   A region: [kp(4)][msub(8)][plane(32)][slot(4)]  (16384B)
//             element(r,k): msub=r>>4, lane=(r&7)*4+(k&3),
//             slot=((r>>3)&1)+2*((k>>2)&1), plane=lane^kp
//   B region: [kp(4)][nsub(16)][plane(32)][slot(2)] (16384B)
//             element(n,k): nsub=n>>3, lane=(n&7)*4+(k&3),
//             slot=(k>>2)&1, plane=lane^kp
// ---------------------------------------------------------------------------
#define STAGE_F 16384         // floats per stage (4 regions x 4096)
#define OFF_ABIG 0
#define OFF_ASML 4096
#define OFF_BBIG 8192
#define OFF_BSML 12288

__global__ __launch_bounds__(256, 1)
void gemm_mma(const float* __restrict__ A, const float* __restrict__ B,
              float* __restrict__ C, int M, int N, int K,
              long long sA, long long sB, long long sC, float alpha)
{
    extern __shared__ float sm[];

    const int tid   = threadIdx.x;
    const int lane  = tid & 31;
    const int warp  = tid >> 5;
    const int warpM = warp >> 1;      // 0..3 -> 32-row slab
    const int warpN = warp & 1;       // 0..1 -> 64-col slab
    const int bz = blockIdx.z;
    A += (long long)bz * sA;
    B += (long long)bz * sB;
    C += (long long)bz * sC;
    const int rowBase = blockIdx.y * 128;
    const int colBase = blockIdx.x * 128;

    // per-thread staging geometry (fixed across chunks)
    const int stR  = tid >> 3;          // 0..31  (+64 per iter pair... see loop)
    const int stKQ = (tid & 7) * 4;     // 0,4,...,28
    const int stKP = stKQ >> 3;         // 0..3
    const int stSK = (stKQ >> 2) & 1;   // slotk

    float4 va[4], vb[4];

    // ---- load chunk k0 into registers (guarded, zero-filled) ----
    auto loadChunk = [&](int k0) {
        #pragma unroll
        for (int i = 0; i < 4; i++) {
            int r = stR + i * 32;
            va[i] = make_float4(0.f, 0.f, 0.f, 0.f);
            if (rowBase + r < M && k0 + stKQ < K)
                va[i] = *(const float4*)(A + (size_t)(rowBase + r) * K + k0 + stKQ);
            vb[i] = make_float4(0.f, 0.f, 0.f, 0.f);
            if (colBase + r < N && k0 + stKQ < K)
                vb[i] = *(const float4*)(B + (size_t)(colBase + r) * K + k0 + stKQ);
        }
    };

    // ---- split + store registers into fragment-order smem stage ----
    auto stsChunk = [&](float* stg) {
        #pragma unroll
        for (int i = 0; i < 4; i++) {
            int r = stR + i * 32;
            // A element (r, stKQ + j)
            {
                int msub  = r >> 4;
                int rm    = r & 15;
                int laneb = (rm & 7) * 4;
                int slot  = ((rm >> 3) & 1) + 2 * stSK;
                int sub   = (stKP * 8 + msub) * 128;
                float big[4], sml[4];
                big[0] = tf32big(va[i].x); sml[0] = va[i].x - big[0];
                big[1] = tf32big(va[i].y); sml[1] = va[i].y - big[1];
                big[2] = tf32big(va[i].z); sml[2] = va[i].z - big[2];
                big[3] = tf32big(va[i].w); sml[3] = va[i].w - big[3];
                #pragma unroll
                for (int j = 0; j < 4; j++) {
                    int f = sub + ((laneb + j) ^ stKP) * 4 + slot;
                    stg[OFF_ABIG + f] = big[j];
                    stg[OFF_ASML + f] = sml[j];
                }
            }
            // B element (n=r, stKQ + j)
            {
                int nsub  = r >> 3;
                int laneb = (r & 7) * 4;
                int sub   = (stKP * 16 + nsub) * 64;
                float big[4], sml[4];
                big[0] = tf32big(vb[i].x); sml[0] = vb[i].x - big[0];
                big[1] = tf32big(vb[i].y); sml[1] = vb[i].y - big[1];
                big[2] = tf32big(vb[i].z); sml[2] = vb[i].z - big[2];
                big[3] = tf32big(vb[i].w); sml[3] = vb[i].w - big[3];
                #pragma unroll
                for (int j = 0; j < 4; j++) {
                    int f = sub + ((laneb + j) ^ stKP) * 2 + stSK;
                    stg[OFF_BBIG + f] = big[j];
                    stg[OFF_BSML + f] = sml[j];
                }
            }
        }
    };

    float acc[2][8][4];
    #pragma unroll
    for (int i = 0; i < 2; i++)
        #pragma unroll
        for (int j = 0; j < 8; j++)
            #pragma unroll
            for (int q = 0; q < 4; q++) acc[i][j][q] = 0.0f;

    const int KC = (K + 31) >> 5;

    loadChunk(0);
    stsChunk(sm);
    __syncthreads();

    for (int kc = 0; kc < KC; kc++) {
        float* cur = sm + (kc & 1) * STAGE_F;
        float* nxt = sm + ((kc + 1) & 1) * STAGE_F;
        const bool more = (kc + 1) < KC;
        if (more) loadChunk((kc + 1) * 32);

        #pragma unroll
        for (int kp = 0; kp < 4; kp++) {
            // fragment loads
            uint32_t Ab[2][4], As_[2][4], Bb[8][2], Bs[8][2];
            #pragma unroll
            for (int mt = 0; mt < 2; mt++) {
                int base = ((kp * 8 + warpM * 2 + mt) * 32 + (lane ^ kp)) * 4;
                float4 b4 = *(const float4*)&cur[OFF_ABIG + base];
                float4 s4 = *(const float4*)&cur[OFF_ASML + base];
                Ab[mt][0] = __float_as_uint(b4.x); Ab[mt][1] = __float_as_uint(b4.y);
                Ab[mt][2] = __float_as_uint(b4.z); Ab[mt][3] = __float_as_uint(b4.w);
                As_[mt][0] = __float_as_uint(s4.x); As_[mt][1] = __float_as_uint(s4.y);
                As_[mt][2] = __float_as_uint(s4.z); As_[mt][3] = __float_as_uint(s4.w);
            }
            #pragma unroll
            for (int nt = 0; nt < 8; nt++) {
                int base = ((kp * 16 + warpN * 8 + nt) * 32 + (lane ^ kp)) * 2;
                float2 b2 = *(const float2*)&cur[OFF_BBIG + base];
                float2 s2 = *(const float2*)&cur[OFF_BSML + base];
                Bb[nt][0] = __float_as_uint(b2.x); Bb[nt][1] = __float_as_uint(b2.y);
                Bs[nt][0] = __float_as_uint(s2.x); Bs[nt][1] = __float_as_uint(s2.y);
            }
            // 3xTF32: D += Ab*Bb + Ab*Bs + As*Bb
            #pragma unroll
            for (int mt = 0; mt < 2; mt++)
                #pragma unroll
                for (int nt = 0; nt < 8; nt++) {
                    mma8(acc[mt][nt], Ab[mt], Bb[nt]);
                    mma8(acc[mt][nt], Ab[mt], Bs[nt]);
                    mma8(acc[mt][nt], As_[mt], Bb[nt]);
                }
            if (kp == 2 && more) stsChunk(nxt);
        }
        __syncthreads();
    }

    // ---- epilogue from register accumulators ----
    const int grp = lane >> 2;
    const int qid = lane & 3;
    #pragma unroll
    for (int mt = 0; mt < 2; mt++) {
        #pragma unroll
        for (int nt = 0; nt < 8; nt++) {
            int r = rowBase + warpM * 32 + mt * 16 + grp;
            int c = colBase + warpN * 64 + nt * 8 + qid * 2;
            if (c < N) {   // N even, c even -> pair safe
                if (r < M) {
                    float2 v = make_float2(acc[mt][nt][0] * alpha, acc[mt][nt][1] * alpha);
                    *(float2*)(C + (size_t)r * N + c) = v;
                }
                if (r + 8 < M) {
                    float2 v = make_float2(acc[mt][nt][2] * alpha, acc[mt][nt][3] * alpha);
                    *(float2*)(C + (size_t)(r + 8) * N + c) = v;
                }
            }
        }
    }
}

// ---------------------------------------------------------------------------
// Transpose: in [R,C] -> out [C,R], batched via blockIdx.z (stride R*C).
// ---------------------------------------------------------------------------
__global__ __launch_bounds__(256)
void transpose_k(const float* __restrict__ in, float* __restrict__ out, int R, int C)
{
    __shared__ float t[32][33];
    const long long bo = (long long)blockIdx.z * R * C;
    in  += bo;
    out += bo;
    int c0 = blockIdx.x * 32, r0 = blockIdx.y * 32;
    int x = c0 + threadIdx.x;
    #pragma unroll
    for (int i = 0; i < 32; i += 8) {
        int y = r0 + threadIdx.y + i;
        if (y < R && x < C) t[threadIdx.y + i][threadIdx.x] = in[(size_t)y * C + x];
    }
    __syncthreads();
    x = r0 + threadIdx.x;
    #pragma unroll
    for (int i = 0; i < 32; i += 8) {
        int y = c0 + threadIdx.y + i;
        if (y < C && x < R) out[(size_t)y * R + x] = t[threadIdx.x][threadIdx.y + i];
    }
}

// ---------------------------------------------------------------------------
// Row softmax over length TT=1380, one block (256 threads) per row.
// ---------------------------------------------------------------------------
#define SM_ITER 6
__global__ __launch_bounds__(256)
void softmax_kernel(float* __restrict__ S)
{
    const int row = blockIdx.x;
    float* p = S + (size_t)row * TT;
    const int tid = threadIdx.x;

    float v[SM_ITER];
    float m = -1e30f;
    #pragma unroll
    for (int i = 0; i < SM_ITER; i++) {
        int idx = tid + i * 256;
        v[i] = (idx < TT) ? p[idx] : -1e30f;
        m = fmaxf(m, v[i]);
    }

    __shared__ float red[8];
    #pragma unroll
    for (int o = 16; o > 0; o >>= 1) m = fmaxf(m, __shfl_xor_sync(0xffffffffu, m, o));
    if ((tid & 31) == 0) red[tid >> 5] = m;
    __syncthreads();
    float bm = red[0];
    #pragma unroll
    for (int w = 1; w < 8; w++) bm = fmaxf(bm, red[w]);
    __syncthreads();

    float s = 0.f;
    #pragma unroll
    for (int i = 0; i < SM_ITER; i++) {
        v[i] = __expf(v[i] - bm);
        s += v[i];
    }
    #pragma unroll
    for (int o = 16; o > 0; o >>= 1) s += __shfl_xor_sync(0xffffffffu, s, o);
    if ((tid & 31) == 0) red[tid >> 5] = s;
    __syncthreads();
    float tot = 0.f;
    #pragma unroll
    for (int w = 0; w < 8; w++) tot += red[w];
    float inv = 1.0f / tot;

    #pragma unroll
    for (int i = 0; i < SM_ITER; i++) {
        int idx = tid + i * 256;
        if (idx < TT) p[idx] = v[i] * inv;
    }
}

// ---------------------------------------------------------------------------
extern "C" void kernel_launch(void* const* d_in, const int* in_sizes, int n_in,
                              void* d_out, int out_size)
{
    const float *X = nullptr, *H = nullptr, *W1 = nullptr, *W2 = nullptr;
    for (int i = 0; i < n_in; i++) {
        int s = in_sizes[i];
        if      (s == NB * TT * XDIM) X  = (const float*)d_in[i];
        else if (s == NB * TT * HDIM) H  = (const float*)d_in[i];
        else if (s == XDIM * HDIM)    W1 = (const float*)d_in[i];
        else if (s == CNUM * TT)      W2 = (const float*)d_in[i];
    }
    float* out = (float*)d_out;

    float *T1, *Y, *S, *XT, *HT, *W1T;
    cudaGetSymbolAddress((void**)&T1,  g_T1);
    cudaGetSymbolAddress((void**)&Y,   g_Y);
    cudaGetSymbolAddress((void**)&S,   g_S);
    cudaGetSymbolAddress((void**)&XT,  g_XT);
    cudaGetSymbolAddress((void**)&HT,  g_HT);
    cudaGetSymbolAddress((void**)&W1T, g_W1T);

    const float scale = (float)(1.0 / sqrt((double)XDIM * (double)HDIM));

    const int SMEM = 2 * STAGE_F * (int)sizeof(float);   // 131072
    static bool attr_done = false;
    if (!attr_done) {
        cudaFuncSetAttribute(gemm_mma, cudaFuncAttributeMaxDynamicSharedMemorySize, SMEM);
        attr_done = true;
    }

    // Transposes: XT[B,96,1380], HT[B,192,1380], W1T[192,96]
    transpose_k<<<dim3(3, 44, NB), dim3(32, 8)>>>(X, XT, TT, XDIM);
    transpose_k<<<dim3(6, 44, NB), dim3(32, 8)>>>(H, HT, TT, HDIM);
    transpose_k<<<dim3(6, 3, 1),   dim3(32, 8)>>>(W1, W1T, XDIM, HDIM);

    // K1: T1[b] = W2 @ X[b]   : A=W2[345,1380] (bcast), B=XT[b][96,1380]
    gemm_mma<<<dim3(1, 3, NB), 256, SMEM>>>(
        W2, XT, T1, CNUM, XDIM, TT,
        0LL, (long long)XDIM * TT, (long long)CNUM * XDIM, 1.0f);

    // K2: Y[b] = T1[b] @ W1   : A=T1[b][345,96], B=W1T[192,96] (bcast)
    gemm_mma<<<dim3(2, 3, NB), 256, SMEM>>>(
        T1, W1T, Y, CNUM, HDIM, XDIM,
        (long long)CNUM * XDIM, 0LL, (long long)CNUM * HDIM, 1.0f);

    // K3: S[b] = scale * Y[b] @ H[b]^T : A=Y[b][345,192], B=H[b][1380,192]
    gemm_mma<<<dim3(11, 3, NB), 256, SMEM>>>(
        Y, H, S, CNUM, TT, HDIM,
        (long long)CNUM * HDIM, (long long)TT * HDIM, (long long)CNUM * TT, scale);

    // K4: softmax rows of S (in place)
    softmax_kernel<<<NB * CNUM, 256>>>(S);

    // K5: out[b] = P[b] @ H[b] : A=S[b][345,1380], B=HT[b][192,1380]
    gemm_mma<<<dim3(2, 3, NB), 256, SMEM>>>(
        S, HT, out, CNUM, HDIM, TT,
        (long long)CNUM * TT, (long long)HDIM * TT, (long long)CNUM * HDIM, 1.0f);
}

// round 13
// speedup vs baseline: 4.6435x; 1.6219x over previous
#include <cuda_runtime.h>
#include <cuda_fp16.h>
#include <cstdint>
#include <math.h>

#define NB   64
#define TT   1380
#define XDIM 96
#define HDIM 192
#define CNUM 345

// ---------------- scratch (allocation-free) ----------------
__device__ __align__(128) float g_T1 [(size_t)NB * CNUM * XDIM];   // [B,345,96]
__device__ __align__(128) float g_Y  [(size_t)NB * CNUM * HDIM];   // [B,345,192]
__device__ __align__(128) float g_S  [(size_t)NB * CNUM * TT];     // [B,345,1380]
__device__ __align__(128) float g_XT [(size_t)NB * XDIM * TT];     // [B,96,1380]
__device__ __align__(128) float g_HT [(size_t)NB * HDIM * TT];     // [B,192,1380]
__device__ __align__(128) float g_W1T[(size_t)HDIM * XDIM];        // [192,96]

// half2 split: f = big + sml, both fp16. Products exact in fp32 accum;
// dropped sml*sml term is O(2^-22) => ~fp32 GEMM accuracy with 3 MMAs.
__device__ __forceinline__ void split_h2(float f0, float f1, uint32_t& big, uint32_t& sml) {
    __half2 bh = __floats2half2_rn(f0, f1);
    float2 bf = __half22float2(bh);
    __half2 sh = __floats2half2_rn(f0 - bf.x, f1 - bf.y);
    big = *(uint32_t*)&bh;
    sml = *(uint32_t*)&sh;
}

__device__ __forceinline__ void mma16(float* c, const uint32_t* a, const uint32_t* b) {
    asm volatile(
        "mma.sync.aligned.m16n8k16.row.col.f32.f16.f16.f32 "
        "{%0,%1,%2,%3}, {%4,%5,%6,%7}, {%8,%9}, {%0,%1,%2,%3};"
        : "+f"(c[0]), "+f"(c[1]), "+f"(c[2]), "+f"(c[3])
        : "r"(a[0]), "r"(a[1]), "r"(a[2]), "r"(a[3]), "r"(b[0]), "r"(b[1]));
}

// ---------------------------------------------------------------------------
// Split-precision (3xFP16) mma.sync GEMM:
//   C[M,N] = alpha * A[M,K] @ B[N,K]^T    (both operands K-major fp32)
// CTA tile 128x128, K-chunk 32 (2 phases of k16), 16 warps (warp tile 32x32).
// Smem holds half2 (k,k+1) units in MMA fragment order:
//   A region (u32 units): [kp(2)][msub(8)][plane(32)][slot(4)]  = 2048 u32
//     unit(r,kk): msub=r>>4, rm=r&15, lane=(rm&7)*4+(kki&3),
//                 slot=((rm>>3)&1)+2*((kki>>2)&1), plane=lane^kp, kki=kk&7
//   B region: [kp(2)][nsub(16)][plane(32)][slot(2)] = 2048 u32
//     unit(n,kk): nsub=n>>3, lane=(n&7)*4+(kki&3), slot=(kki>>2)&1
// Fragment reads: A = one uint4 LDS128 (a0..a3), B = one uint2 LDS64 (b0,b1),
// conflict-free. Double-buffered stages (32KB each) + register prefetch.
// ---------------------------------------------------------------------------
#define STAGE_U 8192          // u32 per stage (4 regions x 2048)
#define OFF_ABIG 0
#define OFF_ASML 2048
#define OFF_BBIG 4096
#define OFF_BSML 6144

__global__ __launch_bounds__(512, 1)
void gemm_mma(const float* __restrict__ A, const float* __restrict__ B,
              float* __restrict__ C, int M, int N, int K,
              long long sA, long long sB, long long sC, float alpha)
{
    extern __shared__ uint32_t sm[];

    const int tid   = threadIdx.x;
    const int lane  = tid & 31;
    const int warp  = tid >> 5;
    const int warpM = warp >> 2;      // 0..3 -> 32-row slab
    const int warpN = warp & 3;       // 0..3 -> 32-col slab
    const int bz = blockIdx.z;
    A += (long long)bz * sA;
    B += (long long)bz * sB;
    C += (long long)bz * sC;
    const int rowBase = blockIdx.y * 128;
    const int colBase = blockIdx.x * 128;

    // staging geometry: thread covers (r = tid>>3 + i*64, k = (tid&7)*4 .. +3)
    const int stR  = tid >> 3;          // 0..63
    const int stKQ = (tid & 7) * 4;     // 0,4,...,28
    const int kk0  = stKQ >> 1;         // even unit index 0..14

    float4 va[2], vb[2];

    auto loadChunk = [&](int k0) {
        #pragma unroll
        for (int i = 0; i < 2; i++) {
            int r = stR + i * 64;
            va[i] = make_float4(0.f, 0.f, 0.f, 0.f);
            if (rowBase + r < M && k0 + stKQ < K)
                va[i] = *(const float4*)(A + (size_t)(rowBase + r) * K + k0 + stKQ);
            vb[i] = make_float4(0.f, 0.f, 0.f, 0.f);
            if (colBase + r < N && k0 + stKQ < K)
                vb[i] = *(const float4*)(B + (size_t)(colBase + r) * K + k0 + stKQ);
        }
    };

    auto stsChunk = [&](uint32_t* stg) {
        #pragma unroll
        for (int i = 0; i < 2; i++) {
            int r = stR + i * 64;
            #pragma unroll
            for (int j = 0; j < 2; j++) {        // unit kk = kk0 + j
                int kk  = kk0 + j;
                int kp  = kk >> 3;
                int kki = kk & 7;
                float f0 = j ? va[i].z : va[i].x;
                float f1 = j ? va[i].w : va[i].y;
                uint32_t big, sml;
                split_h2(f0, f1, big, sml);
                {   // A unit
                    int msub = r >> 4, rm = r & 15;
                    int ln   = (rm & 7) * 4 + (kki & 3);
                    int slot = ((rm >> 3) & 1) + 2 * ((kki >> 2) & 1);
                    int idx  = ((kp * 8 + msub) * 32 + (ln ^ kp)) * 4 + slot;
                    stg[OFF_ABIG + idx] = big;
                    stg[OFF_ASML + idx] = sml;
                }
                float g0 = j ? vb[i].z : vb[i].x;
                float g1 = j ? vb[i].w : vb[i].y;
                split_h2(g0, g1, big, sml);
                {   // B unit
                    int nsub = r >> 3;
                    int ln   = (r & 7) * 4 + (kki & 3);
                    int slot = (kki >> 2) & 1;
                    int idx  = ((kp * 16 + nsub) * 32 + (ln ^ kp)) * 2 + slot;
                    stg[OFF_BBIG + idx] = big;
                    stg[OFF_BSML + idx] = sml;
                }
            }
        }
    };

    float acc[2][4][4];
    #pragma unroll
    for (int i = 0; i < 2; i++)
        #pragma unroll
        for (int j = 0; j < 4; j++)
            #pragma unroll
            for (int q = 0; q < 4; q++) acc[i][j][q] = 0.0f;

    const int KC = (K + 31) >> 5;

    loadChunk(0);
    stsChunk(sm);
    __syncthreads();

    for (int kc = 0; kc < KC; kc++) {
        uint32_t* cur = sm + (kc & 1) * STAGE_U;
        uint32_t* nxt = sm + ((kc + 1) & 1) * STAGE_U;
        const bool more = (kc + 1) < KC;
        if (more) loadChunk((kc + 1) * 32);

        #pragma unroll
        for (int kp = 0; kp < 2; kp++) {
            uint32_t Ab[2][4], As_[2][4], Bb[4][2], Bs[4][2];
            #pragma unroll
            for (int mt = 0; mt < 2; mt++) {
                int base = ((kp * 8 + warpM * 2 + mt) * 32 + (lane ^ kp)) * 4;
                uint4 b4 = *(const uint4*)&cur[OFF_ABIG + base];
                uint4 s4 = *(const uint4*)&cur[OFF_ASML + base];
                Ab[mt][0] = b4.x; Ab[mt][1] = b4.y; Ab[mt][2] = b4.z; Ab[mt][3] = b4.w;
                As_[mt][0] = s4.x; As_[mt][1] = s4.y; As_[mt][2] = s4.z; As_[mt][3] = s4.w;
            }
            #pragma unroll
            for (int nt = 0; nt < 4; nt++) {
                int base = ((kp * 16 + warpN * 4 + nt) * 32 + (lane ^ kp)) * 2;
                uint2 b2 = *(const uint2*)&cur[OFF_BBIG + base];
                uint2 s2 = *(const uint2*)&cur[OFF_BSML + base];
                Bb[nt][0] = b2.x; Bb[nt][1] = b2.y;
                Bs[nt][0] = s2.x; Bs[nt][1] = s2.y;
            }
            if (kp == 1 && more) stsChunk(nxt);
            // 3xFP16: D += Ab*Bb + Ab*Bs + As*Bb
            #pragma unroll
            for (int mt = 0; mt < 2; mt++)
                #pragma unroll
                for (int nt = 0; nt < 4; nt++) {
                    mma16(acc[mt][nt], Ab[mt], Bb[nt]);
                    mma16(acc[mt][nt], Ab[mt], Bs[nt]);
                    mma16(acc[mt][nt], As_[mt], Bb[nt]);
                }
        }
        __syncthreads();
    }

    // ---- epilogue from register accumulators ----
    const int grp = lane >> 2;
    const int qid = lane & 3;
    #pragma unroll
    for (int mt = 0; mt < 2; mt++) {
        #pragma unroll
        for (int nt = 0; nt < 4; nt++) {
            int r = rowBase + warpM * 32 + mt * 16 + grp;
            int c = colBase + warpN * 32 + nt * 8 + qid * 2;
            if (c < N) {   // N even, c even -> pair safe
                if (r < M) {
                    float2 v = make_float2(acc[mt][nt][0] * alpha, acc[mt][nt][1] * alpha);
                    *(float2*)(C + (size_t)r * N + c) = v;
                }
                if (r + 8 < M) {
                    float2 v = make_float2(acc[mt][nt][2] * alpha, acc[mt][nt][3] * alpha);
                    *(float2*)(C + (size_t)(r + 8) * N + c) = v;
                }
            }
        }
    }
}

// ---------------------------------------------------------------------------
// Transpose: in [R,C] -> out [C,R], batched via blockIdx.z (stride R*C).
// ---------------------------------------------------------------------------
__global__ __launch_bounds__(256)
void transpose_k(const float* __restrict__ in, float* __restrict__ out, int R, int C)
{
    __shared__ float t[32][33];
    const long long bo = (long long)blockIdx.z * R * C;
    in  += bo;
    out += bo;
    int c0 = blockIdx.x * 32, r0 = blockIdx.y * 32;
    int x = c0 + threadIdx.x;
    #pragma unroll
    for (int i = 0; i < 32; i += 8) {
        int y = r0 + threadIdx.y + i;
        if (y < R && x < C) t[threadIdx.y + i][threadIdx.x] = in[(size_t)y * C + x];
    }
    __syncthreads();
    x = r0 + threadIdx.x;
    #pragma unroll
    for (int i = 0; i < 32; i += 8) {
        int y = c0 + threadIdx.y + i;
        if (y < C && x < R) out[(size_t)y * R + x] = t[threadIdx.x][threadIdx.y + i];
    }
}

// ---------------------------------------------------------------------------
// Row softmax over length TT=1380, one block (256 threads) per row.
// ---------------------------------------------------------------------------
#define SM_ITER 6
__global__ __launch_bounds__(256)
void softmax_kernel(float* __restrict__ S)
{
    const int row = blockIdx.x;
    float* p = S + (size_t)row * TT;
    const int tid = threadIdx.x;

    float v[SM_ITER];
    float m = -1e30f;
    #pragma unroll
    for (int i = 0; i < SM_ITER; i++) {
        int idx = tid + i * 256;
        v[i] = (idx < TT) ? p[idx] : -1e30f;
        m = fmaxf(m, v[i]);
    }

    __shared__ float red[8];
    #pragma unroll
    for (int o = 16; o > 0; o >>= 1) m = fmaxf(m, __shfl_xor_sync(0xffffffffu, m, o));
    if ((tid & 31) == 0) red[tid >> 5] = m;
    __syncthreads();
    float bm = red[0];
    #pragma unroll
    for (int w = 1; w < 8; w++) bm = fmaxf(bm, red[w]);
    __syncthreads();

    float s = 0.f;
    #pragma unroll
    for (int i = 0; i < SM_ITER; i++) {
        v[i] = __expf(v[i] - bm);
        s += v[i];
    }
    #pragma unroll
    for (int o = 16; o > 0; o >>= 1) s += __shfl_xor_sync(0xffffffffu, s, o);
    if ((tid & 31) == 0) red[tid >> 5] = s;
    __syncthreads();
    float tot = 0.f;
    #pragma unroll
    for (int w = 0; w < 8; w++) tot += red[w];
    float inv = 1.0f / tot;

    #pragma unroll
    for (int i = 0; i < SM_ITER; i++) {
        int idx = tid + i * 256;
        if (idx < TT) p[idx] = v[i] * inv;
    }
}

// ---------------------------------------------------------------------------
extern "C" void kernel_launch(void* const* d_in, const int* in_sizes, int n_in,
                              void* d_out, int out_size)
{
    const float *X = nullptr, *H = nullptr, *W1 = nullptr, *W2 = nullptr;
    for (int i = 0; i < n_in; i++) {
        int s = in_sizes[i];
        if      (s == NB * TT * XDIM) X  = (const float*)d_in[i];
        else if (s == NB * TT * HDIM) H  = (const float*)d_in[i];
        else if (s == XDIM * HDIM)    W1 = (const float*)d_in[i];
        else if (s == CNUM * TT)      W2 = (const float*)d_in[i];
    }
    float* out = (float*)d_out;

    float *T1, *Y, *S, *XT, *HT, *W1T;
    cudaGetSymbolAddress((void**)&T1,  g_T1);
    cudaGetSymbolAddress((void**)&Y,   g_Y);
    cudaGetSymbolAddress((void**)&S,   g_S);
    cudaGetSymbolAddress((void**)&XT,  g_XT);
    cudaGetSymbolAddress((void**)&HT,  g_HT);
    cudaGetSymbolAddress((void**)&W1T, g_W1T);

    const float scale = (float)(1.0 / sqrt((double)XDIM * (double)HDIM));

    const int SMEM = 2 * STAGE_U * (int)sizeof(uint32_t);   // 65536
    static bool attr_done = false;
    if (!attr_done) {
        cudaFuncSetAttribute(gemm_mma, cudaFuncAttributeMaxDynamicSharedMemorySize, SMEM);
        attr_done = true;
    }

    // Transposes: XT[B,96,1380], HT[B,192,1380], W1T[192,96]
    transpose_k<<<dim3(3, 44, NB), dim3(32, 8)>>>(X, XT, TT, XDIM);
    transpose_k<<<dim3(6, 44, NB), dim3(32, 8)>>>(H, HT, TT, HDIM);
    transpose_k<<<dim3(6, 3, 1),   dim3(32, 8)>>>(W1, W1T, XDIM, HDIM);

    // K1: T1[b] = W2 @ X[b]   : A=W2[345,1380] (bcast), B=XT[b][96,1380]
    gemm_mma<<<dim3(1, 3, NB), 512, SMEM>>>(
        W2, XT, T1, CNUM, XDIM, TT,
        0LL, (long long)XDIM * TT, (long long)CNUM * XDIM, 1.0f);

    // K2: Y[b] = T1[b] @ W1   : A=T1[b][345,96], B=W1T[192,96] (bcast)
    gemm_mma<<<dim3(2, 3, NB), 512, SMEM>>>(
        T1, W1T, Y, CNUM, HDIM, XDIM,
        (long long)CNUM * XDIM, 0LL, (long long)CNUM * HDIM, 1.0f);

    // K3: S[b] = scale * Y[b] @ H[b]^T : A=Y[b][345,192], B=H[b][1380,192]
    gemm_mma<<<dim3(11, 3, NB), 512, SMEM>>>(
        Y, H, S, CNUM, TT, HDIM,
        (long long)CNUM * HDIM, (long long)TT * HDIM, (long long)CNUM * TT, scale);

    // K4: softmax rows of S (in place)
    softmax_kernel<<<NB * CNUM, 256>>>(S);

    // K5: out[b] = P[b] @ H[b] : A=S[b][345,1380], B=HT[b][192,1380]
    gemm_mma<<<dim3(2, 3, NB), 512, SMEM>>>(
        S, HT, out, CNUM, HDIM, TT,
        (long long)CNUM * TT, (long long)HDIM * TT, (long long)CNUM * HDIM, 1.0f);
}

// round 15
// speedup vs baseline: 5.6610x; 1.2191x over previous
#include <cuda_runtime.h>
#include <cuda_fp16.h>
#include <cstdint>
#include <math.h>

#define NB   64
#define TT   1380
#define XDIM 96
#define HDIM 192
#define CNUM 345

// ---------------- scratch (allocation-free) ----------------
// g_T1 doubles as T1c[345, 6144] (same element count as [64,345,96]).
__device__ __align__(128) float g_T1 [(size_t)NB * CNUM * XDIM];
__device__ __align__(128) float g_Y  [(size_t)NB * CNUM * HDIM];   // [B,345,192]
__device__ __align__(128) float g_S  [(size_t)NB * CNUM * TT];     // [B,345,1380]
__device__ __align__(128) float g_XT [(size_t)NB * XDIM * TT];     // [B,96,1380] == [6144,1380]
__device__ __align__(128) float g_HT [(size_t)NB * HDIM * TT];     // [B,192,1380]
__device__ __align__(128) float g_W1T[(size_t)HDIM * XDIM];        // [192,96]

// half2 split: f = big + sml, both fp16. Products exact in fp32 accum;
// dropped sml*sml term is O(2^-22) => ~fp32 GEMM accuracy with 3 MMAs.
__device__ __forceinline__ void split_h2(float f0, float f1, uint32_t& big, uint32_t& sml) {
    __half2 bh = __floats2half2_rn(f0, f1);
    float2 bf = __half22float2(bh);
    __half2 sh = __floats2half2_rn(f0 - bf.x, f1 - bf.y);
    big = *(uint32_t*)&bh;
    sml = *(uint32_t*)&sh;
}

__device__ __forceinline__ void mma16(float* c, const uint32_t* a, const uint32_t* b) {
    asm volatile(
        "mma.sync.aligned.m16n8k16.row.col.f32.f16.f16.f32 "
        "{%0,%1,%2,%3}, {%4,%5,%6,%7}, {%8,%9}, {%0,%1,%2,%3};"
        : "+f"(c[0]), "+f"(c[1]), "+f"(c[2]), "+f"(c[3])
        : "r"(a[0]), "r"(a[1]), "r"(a[2]), "r"(a[3]), "r"(b[0]), "r"(b[1]));
}

// ---------------------------------------------------------------------------
// Split-precision (3xFP16) mma.sync GEMM:
//   C[M,N] = alpha * A[M,K](lda) @ B[N,K](ldb)^T   (both K-major fp32 views)
// CTA tile 128 x (32*WN); 4 x WN warps, warp tile 32x32; K-chunk 32.
// WN=4: 512 thr, 1 CTA/SM.  WN=2: 256 thr, 2 CTAs/SM (launch_bounds min 2).
// Smem: half2 (k,k+1) units in MMA fragment order, XOR-by-kp plane swizzle;
// A frag = one LDS128, B frag = one LDS64, conflict-free.
// Double-buffered stages + register prefetch of the next chunk.
// ---------------------------------------------------------------------------
template<int WN>
__global__ __launch_bounds__(128 * WN, WN == 2 ? 2 : 1)
void gemm_mma(const float* __restrict__ A, const float* __restrict__ B,
              float* __restrict__ C, int M, int N, int K, int lda, int ldb,
              long long sA, long long sB, long long sC, float alpha)
{
    constexpr int NT  = 32 * WN;            // CTA tile N
    constexpr int NTH = 128 * WN;           // threads
    constexpr int AI  = 1024 / NTH;         // A float4 loads per thread
    constexpr int BI  = (NT * 8) / NTH;     // B float4 loads per thread
    constexpr int RSTEP = NTH / 8;          // row step per iter
    constexpr int OFF_ASML = 2048;
    constexpr int OFF_BBIG = 4096;
    constexpr int OFF_BSML = 4096 + NT * 16;
    constexpr int STAGE_U  = 4096 + NT * 32;

    extern __shared__ uint32_t sm[];

    const int tid   = threadIdx.x;
    const int lane  = tid & 31;
    const int warp  = tid >> 5;
    const int warpM = warp / WN;      // 0..3 -> 32-row slab
    const int warpN = warp % WN;      // 0..WN-1 -> 32-col slab
    const int bz = blockIdx.z;
    A += (long long)bz * sA;
    B += (long long)bz * sB;
    C += (long long)bz * sC;
    const int rowBase = blockIdx.y * 128;
    const int colBase = blockIdx.x * NT;

    const int stR  = tid >> 3;          // base row
    const int stKQ = (tid & 7) * 4;     // k offset 0,4,...,28
    const int kk0  = stKQ >> 1;         // even half2-unit index

    float4 va[AI], vb[BI];

    auto loadChunk = [&](int k0) {
        const bool kok = (k0 + stKQ) < K;
        #pragma unroll
        for (int i = 0; i < AI; i++) {
            int r = stR + i * RSTEP;
            va[i] = make_float4(0.f, 0.f, 0.f, 0.f);
            if (rowBase + r < M && kok)
                va[i] = *(const float4*)(A + (size_t)(rowBase + r) * lda + k0 + stKQ);
        }
        #pragma unroll
        for (int i = 0; i < BI; i++) {
            int r = stR + i * RSTEP;
            vb[i] = make_float4(0.f, 0.f, 0.f, 0.f);
            if (colBase + r < N && kok)
                vb[i] = *(const float4*)(B + (size_t)(colBase + r) * ldb + k0 + stKQ);
        }
    };

    auto stsChunk = [&](uint32_t* stg) {
        #pragma unroll
        for (int i = 0; i < AI; i++) {
            int r = stR + i * RSTEP;
            #pragma unroll
            for (int j = 0; j < 2; j++) {
                int kk  = kk0 + j;
                int kp  = kk >> 3;
                int kki = kk & 7;
                uint32_t big, sml;
                split_h2(j ? va[i].z : va[i].x, j ? va[i].w : va[i].y, big, sml);
                int msub = r >> 4, rm = r & 15;
                int ln   = (rm & 7) * 4 + (kki & 3);
                int slot = ((rm >> 3) & 1) + 2 * ((kki >> 2) & 1);
                int idx  = ((kp * 8 + msub) * 32 + (ln ^ kp)) * 4 + slot;
                stg[idx] = big;
                stg[OFF_ASML + idx] = sml;
            }
        }
        #pragma unroll
        for (int i = 0; i < BI; i++) {
            int r = stR + i * RSTEP;
            #pragma unroll
            for (int j = 0; j < 2; j++) {
                int kk  = kk0 + j;
                int kp  = kk >> 3;
                int kki = kk & 7;
                uint32_t big, sml;
                split_h2(j ? vb[i].z : vb[i].x, j ? vb[i].w : vb[i].y, big, sml);
                int nsub = r >> 3;
                int ln   = (r & 7) * 4 + (kki & 3);
                int slot = (kki >> 2) & 1;
                int idx  = ((kp * (NT / 8) + nsub) * 32 + (ln ^ kp)) * 2 + slot;
                stg[OFF_BBIG + idx] = big;
                stg[OFF_BSML + idx] = sml;
            }
        }
    };

    float acc[2][4][4];
    #pragma unroll
    for (int i = 0; i < 2; i++)
        #pragma unroll
        for (int j = 0; j < 4; j++)
            #pragma unroll
            for (int q = 0; q < 4; q++) acc[i][j][q] = 0.0f;

    const int KC = (K + 31) >> 5;

    loadChunk(0);
    stsChunk(sm);
    __syncthreads();

    for (int kc = 0; kc < KC; kc++) {
        uint32_t* cur = sm + (kc & 1) * STAGE_U;
        uint32_t* nxt = sm + ((kc + 1) & 1) * STAGE_U;
        const bool more = (kc + 1) < KC;
        if (more) loadChunk((kc + 1) * 32);

        #pragma unroll
        for (int kp = 0; kp < 2; kp++) {
            uint32_t Ab[2][4], As_[2][4], Bb[4][2], Bs[4][2];
            #pragma unroll
            for (int mt = 0; mt < 2; mt++) {
                int base = ((kp * 8 + warpM * 2 + mt) * 32 + (lane ^ kp)) * 4;
                uint4 b4 = *(const uint4*)&cur[base];
                uint4 s4 = *(const uint4*)&cur[OFF_ASML + base];
                Ab[mt][0] = b4.x; Ab[mt][1] = b4.y; Ab[mt][2] = b4.z; Ab[mt][3] = b4.w;
                As_[mt][0] = s4.x; As_[mt][1] = s4.y; As_[mt][2] = s4.z; As_[mt][3] = s4.w;
            }
            #pragma unroll
            for (int nt = 0; nt < 4; nt++) {
                int base = ((kp * (NT / 8) + warpN * 4 + nt) * 32 + (lane ^ kp)) * 2;
                uint2 b2 = *(const uint2*)&cur[OFF_BBIG + base];
                uint2 s2 = *(const uint2*)&cur[OFF_BSML + base];
                Bb[nt][0] = b2.x; Bb[nt][1] = b2.y;
                Bs[nt][0] = s2.x; Bs[nt][1] = s2.y;
            }
            if (kp == 1 && more) stsChunk(nxt);
            #pragma unroll
            for (int mt = 0; mt < 2; mt++)
                #pragma unroll
                for (int nt = 0; nt < 4; nt++) {
                    mma16(acc[mt][nt], Ab[mt], Bb[nt]);
                    mma16(acc[mt][nt], Ab[mt], Bs[nt]);
                    mma16(acc[mt][nt], As_[mt], Bb[nt]);
                }
        }
        __syncthreads();
    }

    // ---- epilogue from register accumulators ----
    const int grp = lane >> 2;
    const int qid = lane & 3;
    #pragma unroll
    for (int mt = 0; mt < 2; mt++) {
        #pragma unroll
        for (int nt = 0; nt < 4; nt++) {
            int r = rowBase + warpM * 32 + mt * 16 + grp;
            int c = colBase + warpN * 32 + nt * 8 + qid * 2;
            if (c < N) {   // N even, c even -> pair safe
                if (r < M) {
                    float2 v = make_float2(acc[mt][nt][0] * alpha, acc[mt][nt][1] * alpha);
                    *(float2*)(C + (size_t)r * N + c) = v;
                }
                if (r + 8 < M) {
                    float2 v = make_float2(acc[mt][nt][2] * alpha, acc[mt][nt][3] * alpha);
                    *(float2*)(C + (size_t)(r + 8) * N + c) = v;
                }
            }
        }
    }
}

// ---------------------------------------------------------------------------
// Transpose: in [R,C] -> out [C,R], batched via blockIdx.z (stride R*C).
// ---------------------------------------------------------------------------
__global__ __launch_bounds__(256)
void transpose_k(const float* __restrict__ in, float* __restrict__ out, int R, int C)
{
    __shared__ float t[32][33];
    const long long bo = (long long)blockIdx.z * R * C;
    in  += bo;
    out += bo;
    int c0 = blockIdx.x * 32, r0 = blockIdx.y * 32;
    int x = c0 + threadIdx.x;
    #pragma unroll
    for (int i = 0; i < 32; i += 8) {
        int y = r0 + threadIdx.y + i;
        if (y < R && x < C) t[threadIdx.y + i][threadIdx.x] = in[(size_t)y * C + x];
    }
    __syncthreads();
    x = r0 + threadIdx.x;
    #pragma unroll
    for (int i = 0; i < 32; i += 8) {
        int y = c0 + threadIdx.y + i;
        if (y < C && x < R) out[(size_t)y * R + x] = t[threadIdx.x][threadIdx.y + i];
    }
}

// ---------------------------------------------------------------------------
// Row softmax over length TT=1380, one block (256 threads) per row.
// ---------------------------------------------------------------------------
#define SM_ITER 6
__global__ __launch_bounds__(256)
void softmax_kernel(float* __restrict__ S)
{
    const int row = blockIdx.x;
    float* p = S + (size_t)row * TT;
    const int tid = threadIdx.x;

    float v[SM_ITER];
    float m = -1e30f;
    #pragma unroll
    for (int i = 0; i < SM_ITER; i++) {
        int idx = tid + i * 256;
        v[i] = (idx < TT) ? p[idx] : -1e30f;
        m = fmaxf(m, v[i]);
    }

    __shared__ float red[8];
    #pragma unroll
    for (int o = 16; o > 0; o >>= 1) m = fmaxf(m, __shfl_xor_sync(0xffffffffu, m, o));
    if ((tid & 31) == 0) red[tid >> 5] = m;
    __syncthreads();
    float bm = red[0];
    #pragma unroll
    for (int w = 1; w < 8; w++) bm = fmaxf(bm, red[w]);
    __syncthreads();

    float s = 0.f;
    #pragma unroll
    for (int i = 0; i < SM_ITER; i++) {
        v[i] = __expf(v[i] - bm);
        s += v[i];
    }
    #pragma unroll
    for (int o = 16; o > 0; o >>= 1) s += __shfl_xor_sync(0xffffffffu, s, o);
    if ((tid & 31) == 0) red[tid >> 5] = s;
    __syncthreads();
    float tot = 0.f;
    #pragma unroll
    for (int w = 0; w < 8; w++) tot += red[w];
    float inv = 1.0f / tot;

    #pragma unroll
    for (int i = 0; i < SM_ITER; i++) {
        int idx = tid + i * 256;
        if (idx < TT) p[idx] = v[i] * inv;
    }
}

// ---------------------------------------------------------------------------
extern "C" void kernel_launch(void* const* d_in, const int* in_sizes, int n_in,
                              void* d_out, int out_size)
{
    const float *X = nullptr, *H = nullptr, *W1 = nullptr, *W2 = nullptr;
    for (int i = 0; i < n_in; i++) {
        int s = in_sizes[i];
        if      (s == NB * TT * XDIM) X  = (const float*)d_in[i];
        else if (s == NB * TT * HDIM) H  = (const float*)d_in[i];
        else if (s == XDIM * HDIM)    W1 = (const float*)d_in[i];
        else if (s == CNUM * TT)      W2 = (const float*)d_in[i];
    }
    float* out = (float*)d_out;

    float *T1c, *Y, *S, *XT, *HT, *W1T;
    cudaGetSymbolAddress((void**)&T1c, g_T1);
    cudaGetSymbolAddress((void**)&Y,   g_Y);
    cudaGetSymbolAddress((void**)&S,   g_S);
    cudaGetSymbolAddress((void**)&XT,  g_XT);
    cudaGetSymbolAddress((void**)&HT,  g_HT);
    cudaGetSymbolAddress((void**)&W1T, g_W1T);

    const float scale = (float)(1.0 / sqrt((double)XDIM * (double)HDIM));

    const int SMEM4 = 2 * (4096 + 128 * 32) * (int)sizeof(uint32_t);  // 64KB
    const int SMEM2 = 2 * (4096 + 64  * 32) * (int)sizeof(uint32_t);  // 48KB
    static bool attr_done = false;
    if (!attr_done) {
        cudaFuncSetAttribute(gemm_mma<4>, cudaFuncAttributeMaxDynamicSharedMemorySize, SMEM4);
        cudaFuncSetAttribute(gemm_mma<2>, cudaFuncAttributeMaxDynamicSharedMemorySize, SMEM2);
        attr_done = true;
    }

    // Transposes: XT[B,96,1380] (== [6144,1380]), HT[B,192,1380], W1T[192,96]
    transpose_k<<<dim3(3, 44, NB), dim3(32, 8)>>>(X, XT, TT, XDIM);
    transpose_k<<<dim3(6, 44, NB), dim3(32, 8)>>>(H, HT, TT, HDIM);
    transpose_k<<<dim3(6, 3, 1),   dim3(32, 8)>>>(W1, W1T, XDIM, HDIM);

    // K1 (merged over batch): T1c[345,6144] = W2[345,1380] @ XT_all[6144,1380]^T
    //   N = 6144 = 48 exact 128-tiles; grid 144 = one full wave.
    gemm_mma<4><<<dim3(48, 3, 1), 512, SMEM4>>>(
        W2, XT, T1c, CNUM, NB * XDIM, TT, TT, TT,
        0LL, 0LL, 0LL, 1.0f);

    // K2: Y[b] = T1[b] @ W1  : A = T1c view (lda=6144, batch offset 96), B=W1T (bcast)
    gemm_mma<2><<<dim3(3, 3, NB), 256, SMEM2>>>(
        T1c, W1T, Y, CNUM, HDIM, XDIM, NB * XDIM, XDIM,
        (long long)XDIM, 0LL, (long long)CNUM * HDIM, 1.0f);

    // K3: S[b] = scale * Y[b] @ H[b]^T : A=Y[b][345,192], B=H[b][1380,192]
    gemm_mma<4><<<dim3(11, 3, NB), 512, SMEM4>>>(
        Y, H, S, CNUM, TT, HDIM, HDIM, HDIM,
        (long long)CNUM * HDIM, (long long)TT * HDIM, (long long)CNUM * TT, scale);

    // K4: softmax rows of S (in place)
    softmax_kernel<<<NB * CNUM, 256>>>(S);

    // K5: out[b] = P[b] @ H[b] : A=S[b][345,1380], B=HT[b][192,1380]; N=192=3x64 exact
    gemm_mma<2><<<dim3(3, 3, NB), 256, SMEM2>>>(
        S, HT, out, CNUM, HDIM, TT, TT, TT,
        (long long)CNUM * TT, (long long)HDIM * TT, (long long)CNUM * HDIM, 1.0f);
}